// round 1
// baseline (speedup 1.0000x reference)
#include <cuda_runtime.h>
#include <cuda_bf16.h>

#define K_BONES 512

// Per bone, 4 float4s:
//   [0] = (bx, by, bz, bx^2+by^2+bz^2)
//   [1] = row0 of [R|t] = (R00, R01, R02, t0)
//   [2] = row1 of [R|t]
//   [3] = row2 of [R|t]
__device__ float4 g_bones[K_BONES * 4];

// ---------------------------------------------------------------------------
// Precompute: 6D continuous rotation -> rotmat (Gram-Schmidt), pack with
// translation and bone location + squared norm. 512 threads total; negligible.
// rotcont layout (reshape(3,2) row-major): a1=(p0,p2,p4), a2=(p1,p3,p5).
// rotmat columns are (b1, b2, b3), so row i = (b1[i], b2[i], b3[i]).
// ---------------------------------------------------------------------------
__global__ void prep_kernel(const float* __restrict__ bone_locs,
                            const float* __restrict__ bone_transf,
                            const int* __restrict__ tidx_p) {
    int k = blockIdx.x * blockDim.x + threadIdx.x;
    if (k >= K_BONES) return;
    const float* p = bone_transf + ((long long)tidx_p[0] * K_BONES + k) * 9;

    float a1x = p[0], a2x = p[1];
    float a1y = p[2], a2y = p[3];
    float a1z = p[4], a2z = p[5];

    float n1 = sqrtf(a1x * a1x + a1y * a1y + a1z * a1z) + 1e-12f;
    float b1x = a1x / n1, b1y = a1y / n1, b1z = a1z / n1;

    float d = b1x * a2x + b1y * a2y + b1z * a2z;
    float cx = a2x - d * b1x, cy = a2y - d * b1y, cz = a2z - d * b1z;
    float n2 = sqrtf(cx * cx + cy * cy + cz * cz) + 1e-12f;
    float b2x = cx / n2, b2y = cy / n2, b2z = cz / n2;

    float b3x = b1y * b2z - b1z * b2y;
    float b3y = b1z * b2x - b1x * b2z;
    float b3z = b1x * b2y - b1y * b2x;

    float tx = p[6], ty = p[7], tz = p[8];
    float bx = bone_locs[3 * k + 0];
    float by = bone_locs[3 * k + 1];
    float bz = bone_locs[3 * k + 2];

    g_bones[4 * k + 0] = make_float4(bx, by, bz, bx * bx + by * by + bz * bz);
    g_bones[4 * k + 1] = make_float4(b1x, b2x, b3x, tx);
    g_bones[4 * k + 2] = make_float4(b1y, b2y, b3y, ty);
    g_bones[4 * k + 3] = make_float4(b1z, b2z, b3z, tz);
}

// ---------------------------------------------------------------------------
// Main kernel: 1 point/thread, one-pass no-max softmax fused with the
// transform blend. Bone data in shared (32 KB), broadcast LDS.128 reads.
// out_i = (sum_k e_k * Trow_i) . (x,y,z,1) / sum_k e_k
// ---------------------------------------------------------------------------
__global__ __launch_bounds__(256)
void skin_kernel(const float* __restrict__ xyz,
                 float* __restrict__ out, int n) {
    __shared__ float4 sb[K_BONES * 4];
    for (int i = threadIdx.x; i < K_BONES * 4; i += blockDim.x)
        sb[i] = g_bones[i];
    __syncthreads();

    int idx = blockIdx.x * blockDim.x + threadIdx.x;
    if (idx >= n) return;

    float x = xyz[3 * idx + 0];
    float y = xyz[3 * idx + 1];
    float z = xyz[3 * idx + 2];
    float xx = fmaf(x, x, fmaf(y, y, z * z));

    float s = 0.0f;
    float A0 = 0.f, A1 = 0.f, A2 = 0.f, A3 = 0.f;
    float A4 = 0.f, A5 = 0.f, A6 = 0.f, A7 = 0.f;
    float A8 = 0.f, A9 = 0.f, A10 = 0.f, A11 = 0.f;

    const float C = -28.853900817779268f;  // -SIGMA * log2(e), SIGMA = 20

    #pragma unroll 4
    for (int k = 0; k < K_BONES; k++) {
        float4 b = sb[4 * k + 0];
        float dot = fmaf(x, b.x, fmaf(y, b.y, z * b.z));
        float d2 = fmaf(-2.0f, dot, xx + b.w);
        d2 = fmaxf(d2, 0.0f);
        float dist;
        asm("sqrt.approx.f32 %0, %1;" : "=f"(dist) : "f"(d2));
        float e;
        asm("ex2.approx.f32 %0, %1;" : "=f"(e) : "f"(dist * C));
        s += e;

        float4 r0 = sb[4 * k + 1];
        float4 r1 = sb[4 * k + 2];
        float4 r2 = sb[4 * k + 3];
        A0 = fmaf(e, r0.x, A0);  A1 = fmaf(e, r0.y, A1);
        A2 = fmaf(e, r0.z, A2);  A3 = fmaf(e, r0.w, A3);
        A4 = fmaf(e, r1.x, A4);  A5 = fmaf(e, r1.y, A5);
        A6 = fmaf(e, r1.z, A6);  A7 = fmaf(e, r1.w, A7);
        A8 = fmaf(e, r2.x, A8);  A9 = fmaf(e, r2.y, A9);
        A10 = fmaf(e, r2.z, A10); A11 = fmaf(e, r2.w, A11);
    }

    float inv;
    asm("rcp.approx.f32 %0, %1;" : "=f"(inv) : "f"(s));

    float ox = fmaf(A0, x, fmaf(A1, y, fmaf(A2, z, A3))) * inv;
    float oy = fmaf(A4, x, fmaf(A5, y, fmaf(A6, z, A7))) * inv;
    float oz = fmaf(A8, x, fmaf(A9, y, fmaf(A10, z, A11))) * inv;

    out[3 * idx + 0] = ox;
    out[3 * idx + 1] = oy;
    out[3 * idx + 2] = oz;
}

extern "C" void kernel_launch(void* const* d_in, const int* in_sizes, int n_in,
                              void* d_out, int out_size) {
    const float* xyz  = (const float*)d_in[0];   // [N, 3]
    const float* locs = (const float*)d_in[1];   // [512, 3]
    const float* bt   = (const float*)d_in[2];   // [64, 512, 9]
    const int*   tidx = (const int*)d_in[3];     // scalar

    int n = in_sizes[0] / 3;

    prep_kernel<<<(K_BONES + 255) / 256, 256>>>(locs, bt, tidx);
    skin_kernel<<<(n + 255) / 256, 256>>>(xyz, (float*)d_out, n);
}

// round 2
// speedup vs baseline: 1.0320x; 1.0320x over previous
#include <cuda_runtime.h>
#include <cuda_bf16.h>

#define K_BONES 512

typedef unsigned long long u64;

// Per bone, 4 float4s (64 B), laid out so packed-pairs are natural:
//   [0] = (bx, by, bz, 0)
//   [1] = (R00, R01, R02, t0)   row0 of [R|t]
//   [2] = (R10, R11, R12, t1)
//   [3] = (R20, R21, R22, t2)
__device__ float4 g_bones[K_BONES * 4];

// ---------------------------------------------------------------------------
// Precompute: 6D continuous rotation -> rotmat (Gram-Schmidt), pack with
// translation + bone location. 512 threads total; negligible cost.
// rotcont reshape(3,2) row-major: a1=(p0,p2,p4), a2=(p1,p3,p5).
// rotmat columns are (b1,b2,b3) => row i = (b1[i], b2[i], b3[i]).
// ---------------------------------------------------------------------------
__global__ void prep_kernel(const float* __restrict__ bone_locs,
                            const float* __restrict__ bone_transf,
                            const int* __restrict__ tidx_p) {
    int k = blockIdx.x * blockDim.x + threadIdx.x;
    if (k >= K_BONES) return;
    const float* p = bone_transf + ((long long)tidx_p[0] * K_BONES + k) * 9;

    float a1x = p[0], a2x = p[1];
    float a1y = p[2], a2y = p[3];
    float a1z = p[4], a2z = p[5];

    float n1 = sqrtf(a1x * a1x + a1y * a1y + a1z * a1z) + 1e-12f;
    float b1x = a1x / n1, b1y = a1y / n1, b1z = a1z / n1;

    float d = b1x * a2x + b1y * a2y + b1z * a2z;
    float cx = a2x - d * b1x, cy = a2y - d * b1y, cz = a2z - d * b1z;
    float n2 = sqrtf(cx * cx + cy * cy + cz * cz) + 1e-12f;
    float b2x = cx / n2, b2y = cy / n2, b2z = cz / n2;

    float b3x = b1y * b2z - b1z * b2y;
    float b3y = b1z * b2x - b1x * b2z;
    float b3z = b1x * b2y - b1y * b2x;

    g_bones[4 * k + 0] = make_float4(bone_locs[3 * k + 0], bone_locs[3 * k + 1],
                                     bone_locs[3 * k + 2], 0.0f);
    g_bones[4 * k + 1] = make_float4(b1x, b2x, b3x, p[6]);
    g_bones[4 * k + 2] = make_float4(b1y, b2y, b3y, p[7]);
    g_bones[4 * k + 3] = make_float4(b1z, b2z, b3z, p[8]);
}

// ---- packed f32x2 helpers (sm_100a) ---------------------------------------
__device__ __forceinline__ u64 pk2(float lo, float hi) {
    u64 r;
    asm("mov.b64 %0, {%1, %2};" : "=l"(r) : "f"(lo), "f"(hi));
    return r;
}
__device__ __forceinline__ void upk2(u64 v, float& lo, float& hi) {
    asm("mov.b64 {%0, %1}, %2;" : "=f"(lo), "=f"(hi) : "l"(v));
}
__device__ __forceinline__ u64 addx2(u64 a, u64 b) {
    u64 r;
    asm("add.rn.f32x2 %0, %1, %2;" : "=l"(r) : "l"(a), "l"(b));
    return r;
}
__device__ __forceinline__ u64 mulx2(u64 a, u64 b) {
    u64 r;
    asm("mul.rn.f32x2 %0, %1, %2;" : "=l"(r) : "l"(a), "l"(b));
    return r;
}
__device__ __forceinline__ u64 fmax2(u64 a, u64 b, u64 c) {
    u64 r;
    asm("fma.rn.f32x2 %0, %1, %2, %3;" : "=l"(r) : "l"(a), "l"(b), "l"(c));
    return r;
}

// ---------------------------------------------------------------------------
// Main kernel: 1 point/thread, one-pass no-max softmax fused with the blend.
// Accumulators packed pairwise over matrix columns -> bone pairs (R00,R01)...
// come straight out of the 64-bit lanes of broadcast LDS.128 loads, so packed
// FMA needs NO data duplication. 32 KB smem.
// ---------------------------------------------------------------------------
__global__ __launch_bounds__(256)
void skin_kernel(const float* __restrict__ xyz,
                 float* __restrict__ out, int n) {
    __shared__ ulonglong2 sb[K_BONES * 4];   // 64 B/bone = 32 KB
    {
        const ulonglong2* gb = (const ulonglong2*)g_bones;
        for (int i = threadIdx.x; i < K_BONES * 4; i += blockDim.x)
            sb[i] = gb[i];
    }
    __syncthreads();

    int idx = blockIdx.x * blockDim.x + threadIdx.x;
    if (idx >= n) return;

    float x = xyz[3 * idx + 0];
    float y = xyz[3 * idx + 1];
    float z = xyz[3 * idx + 2];

    u64 nxy = pk2(-x, -y);

    float s = 0.0f;
    u64 A01 = 0ull, A23 = 0ull, A45 = 0ull;
    u64 A67 = 0ull, A89 = 0ull, AAB = 0ull;

    const float C = -28.853900817779268f;  // -SIGMA * log2(e), SIGMA = 20

    const ulonglong2* p = sb;
    #pragma unroll 8
    for (int k = 0; k < K_BONES; k++, p += 4) {
        ulonglong2 qa = p[0];   // (bx,by) | (bz, 0)
        ulonglong2 qb = p[1];   // (R00,R01) | (R02,t0)
        ulonglong2 qc = p[2];   // (R10,R11) | (R12,t1)
        ulonglong2 qd = p[3];   // (R20,R21) | (R22,t2)

        u64 dxy  = addx2(qa.x, nxy);     // (bx-x, by-y)
        float bz, pad;  upk2(qa.y, bz, pad);
        float dz = bz - z;
        u64 dxy2 = mulx2(dxy, dxy);
        float t0, t1;   upk2(dxy2, t0, t1);
        float d2 = fmaf(dz, dz, t0) + t1;     // exact diff form: >= 0 always

        float dist;
        asm("sqrt.approx.f32 %0, %1;" : "=f"(dist) : "f"(d2));
        float e;
        asm("ex2.approx.f32 %0, %1;" : "=f"(e) : "f"(dist * C));

        s += e;
        u64 e2 = pk2(e, e);
        A01 = fmax2(e2, qb.x, A01);
        A23 = fmax2(e2, qb.y, A23);
        A45 = fmax2(e2, qc.x, A45);
        A67 = fmax2(e2, qc.y, A67);
        A89 = fmax2(e2, qd.x, A89);
        AAB = fmax2(e2, qd.y, AAB);
    }

    float inv;
    asm("rcp.approx.f32 %0, %1;" : "=f"(inv) : "f"(s));

    float A0, A1, A2, A3, A4, A5, A6, A7, A8, A9, A10, A11;
    upk2(A01, A0, A1);   upk2(A23, A2, A3);
    upk2(A45, A4, A5);   upk2(A67, A6, A7);
    upk2(A89, A8, A9);   upk2(AAB, A10, A11);

    float ox = fmaf(A0, x, fmaf(A1, y, fmaf(A2, z, A3))) * inv;
    float oy = fmaf(A4, x, fmaf(A5, y, fmaf(A6, z, A7))) * inv;
    float oz = fmaf(A8, x, fmaf(A9, y, fmaf(A10, z, A11))) * inv;

    out[3 * idx + 0] = ox;
    out[3 * idx + 1] = oy;
    out[3 * idx + 2] = oz;
}

extern "C" void kernel_launch(void* const* d_in, const int* in_sizes, int n_in,
                              void* d_out, int out_size) {
    const float* xyz  = (const float*)d_in[0];   // [N, 3]
    const float* locs = (const float*)d_in[1];   // [512, 3]
    const float* bt   = (const float*)d_in[2];   // [64, 512, 9]
    const int*   tidx = (const int*)d_in[3];     // scalar

    int n = in_sizes[0] / 3;

    prep_kernel<<<(K_BONES + 255) / 256, 256>>>(locs, bt, tidx);
    skin_kernel<<<(n + 255) / 256, 256>>>(xyz, (float*)d_out, n);
}